// round 17
// baseline (speedup 1.0000x reference)
#include <cuda_runtime.h>
#include <cstdint>
#include <cstddef>

// Problem dims
#define VOCAB 32000
#define EMB   512
#define HID   512
#define BATCH 64
#define S_LEN 512

// ---------------------------------------------------------------------------
// Scratch (no allocation allowed -> __device__ global)
// ---------------------------------------------------------------------------
__device__ float g_xproj[(size_t)BATCH * S_LEN * HID]; // 64 MB scratch

// ---------------------------------------------------------------------------
// Packed f32x2 helpers (Blackwell)
// ---------------------------------------------------------------------------
__device__ __forceinline__ unsigned long long packdup(float v) {
    unsigned long long r;
    asm("mov.b64 %0, {%1, %1};" : "=l"(r) : "f"(v));
    return r;
}
__device__ __forceinline__ void ffma2(unsigned long long& acc,
                                      unsigned long long a,
                                      unsigned long long b) {
    asm("fma.rn.f32x2 %0, %1, %2, %0;" : "+l"(acc) : "l"(a), "l"(b));
}
__device__ __forceinline__ float2 unpack2(unsigned long long v) {
    float2 f;
    asm("mov.b64 {%0, %1}, %2;" : "=f"(f.x), "=f"(f.y) : "l"(v));
    return f;
}

// ---------------------------------------------------------------------------
// Kernel 1: x_proj = gather(emb, tok) @ W_ih^T + (b_ih + b_hh)
// (R16's two-stage pipelined version, unchanged)
// ---------------------------------------------------------------------------
__global__ void __launch_bounds__(256, 2)
xproj_kernel(const void* __restrict__ tok_raw,
             const float* __restrict__ emb,
             const float* __restrict__ W_ih,
             const float* __restrict__ b_ih,
             const float* __restrict__ b_hh)
{
    __shared__ float              As[2][16][128];
    __shared__ unsigned long long Bsd[2][16][128];
    __shared__ int                toks[128];
    __shared__ int                s_tok64;

    const int tid = threadIdx.x;
    const int m0  = blockIdx.y * 128;
    const int n0  = blockIdx.x * 128;

    if (tid < 32) {
        int wv = ((const int*)tok_raw)[2 * tid + 1];
        unsigned nz = __ballot_sync(0xffffffffu, wv != 0);
        if (tid == 0) s_tok64 = (nz == 0u);
    }
    __syncthreads();

    if (tid < 128) {
        int m = m0 + tid;
        toks[tid] = s_tok64 ? (int)((const long long*)tok_raw)[m]
                            : ((const int*)tok_raw)[m];
    }
    __syncthreads();

    const int ldr_m   = tid & 127;
    const int ldr_seg = (tid >> 7) * 8;
    const float* arow_base = emb  + (size_t)toks[ldr_m] * EMB + ldr_seg;
    const float* brow_base = W_ih + (size_t)(n0 + ldr_m) * EMB + ldr_seg;

    const int ty = tid & 15;
    const int tx = tid >> 4;

    unsigned long long acc[32];
#pragma unroll
    for (int i = 0; i < 32; i++) acc[i] = 0ull;

    float4 av0, av1, bv0, bv1;

#define STS_TILE(st)                                                   \
    do {                                                               \
        As[st][ldr_seg + 0][ldr_m] = av0.x;                            \
        As[st][ldr_seg + 1][ldr_m] = av0.y;                            \
        As[st][ldr_seg + 2][ldr_m] = av0.z;                            \
        As[st][ldr_seg + 3][ldr_m] = av0.w;                            \
        As[st][ldr_seg + 4][ldr_m] = av1.x;                            \
        As[st][ldr_seg + 5][ldr_m] = av1.y;                            \
        As[st][ldr_seg + 6][ldr_m] = av1.z;                            \
        As[st][ldr_seg + 7][ldr_m] = av1.w;                            \
        Bsd[st][ldr_seg + 0][ldr_m] = packdup(bv0.x);                  \
        Bsd[st][ldr_seg + 1][ldr_m] = packdup(bv0.y);                  \
        Bsd[st][ldr_seg + 2][ldr_m] = packdup(bv0.z);                  \
        Bsd[st][ldr_seg + 3][ldr_m] = packdup(bv0.w);                  \
        Bsd[st][ldr_seg + 4][ldr_m] = packdup(bv1.x);                  \
        Bsd[st][ldr_seg + 5][ldr_m] = packdup(bv1.y);                  \
        Bsd[st][ldr_seg + 6][ldr_m] = packdup(bv1.z);                  \
        Bsd[st][ldr_seg + 7][ldr_m] = packdup(bv1.w);                  \
    } while (0)

#define LDG_TILE(kt)                                                   \
    do {                                                               \
        const int _k0 = (kt) * 16;                                     \
        av0 = *(const float4*)(arow_base + _k0);                       \
        av1 = *(const float4*)(arow_base + _k0 + 4);                   \
        bv0 = *(const float4*)(brow_base + _k0);                       \
        bv1 = *(const float4*)(brow_base + _k0 + 4);                   \
    } while (0)

    LDG_TILE(0);
    STS_TILE(0);
    LDG_TILE(1);
    __syncthreads();

    const int NKT = EMB / 16;
    for (int kt = 0; kt < NKT; kt++) {
        const int st = kt & 1;
#pragma unroll
        for (int kk = 0; kk < 16; kk++) {
            ulonglong2 a01 = *(const ulonglong2*)&As[st][kk][ty * 8];
            ulonglong2 a23 = *(const ulonglong2*)&As[st][kk][ty * 8 + 4];
            unsigned long long ap[4] = { a01.x, a01.y, a23.x, a23.y };
            ulonglong2 b01 = *(const ulonglong2*)&Bsd[st][kk][tx * 8];
            ulonglong2 b23 = *(const ulonglong2*)&Bsd[st][kk][tx * 8 + 2];
            ulonglong2 b45 = *(const ulonglong2*)&Bsd[st][kk][tx * 8 + 4];
            ulonglong2 b67 = *(const ulonglong2*)&Bsd[st][kk][tx * 8 + 6];
            unsigned long long bd[8] = { b01.x, b01.y, b23.x, b23.y,
                                         b45.x, b45.y, b67.x, b67.y };
#pragma unroll
            for (int i2 = 0; i2 < 4; i2++)
#pragma unroll
                for (int j = 0; j < 8; j++)
                    ffma2(acc[i2 * 8 + j], ap[i2], bd[j]);
        }
        if (kt + 1 < NKT) {
            STS_TILE((kt + 1) & 1);
            if (kt + 2 < NKT) LDG_TILE(kt + 2);
            __syncthreads();
        }
    }
#undef STS_TILE
#undef LDG_TILE

    float bias[8];
    {
        float4 x0 = *(const float4*)(b_ih + n0 + tx * 8);
        float4 x1 = *(const float4*)(b_ih + n0 + tx * 8 + 4);
        float4 y0 = *(const float4*)(b_hh + n0 + tx * 8);
        float4 y1 = *(const float4*)(b_hh + n0 + tx * 8 + 4);
        bias[0] = x0.x + y0.x;  bias[1] = x0.y + y0.y;
        bias[2] = x0.z + y0.z;  bias[3] = x0.w + y0.w;
        bias[4] = x1.x + y1.x;  bias[5] = x1.y + y1.y;
        bias[6] = x1.z + y1.z;  bias[7] = x1.w + y1.w;
    }
#pragma unroll
    for (int i2 = 0; i2 < 4; i2++) {
        float r0[8], r1[8];
#pragma unroll
        for (int j = 0; j < 8; j++) {
            float2 f = unpack2(acc[i2 * 8 + j]);
            r0[j] = f.x + bias[j];
            r1[j] = f.y + bias[j];
        }
        size_t mg = (size_t)(m0 + ty * 8 + i2 * 2);
        float* o0 = g_xproj + mg * HID + n0 + tx * 8;
        float* o1 = o0 + HID;
        *(float4*)(o0)     = make_float4(r0[0], r0[1], r0[2], r0[3]);
        *(float4*)(o0 + 4) = make_float4(r0[4], r0[5], r0[6], r0[7]);
        *(float4*)(o1)     = make_float4(r1[0], r1[1], r1[2], r1[3]);
        *(float4*)(o1 + 4) = make_float4(r1[4], r1[5], r1[6], r1[7]);
    }
}

// ---------------------------------------------------------------------------
// Kernel 2: recurrence, WARP-SPECIALIZED 2-GROUP PIPELINE.
// 16 clusters x 8 CTAs x 320 threads.
//  - tid<256: COMPUTE warps (R16's W layout: thread holds W_hh rows 64w+lane,
//    +32 over cols [64*rank,+64)). Per step, for group g in {A={b0,b1},
//    B={b2,b3}}: bar.sync(1+g) for h_pub[g], 128 FFMA2, stage 512B,
//    warp-autonomous bulk send to owner CTA w. Never touches an mbar.
//  - tid>=256 (64 threads): REDUCE warps. Wait mbar(g,s) (poll runs parallel
//    to compute), re-arm, reduce 8 slabs + xp, tanh, publish h_pub, STG out,
//    bar.arrive(1+g). The flight+wake is off the compute warps' stream.
// No __syncthreads in the main loop.
// ---------------------------------------------------------------------------
#define CSZ 8
#define NG  2
#define GB  2
#define GRP_TX 4096               /* 8 slabs x 512 B per owner per group-step */

__global__ void __cluster_dims__(CSZ, 1, 1) __launch_bounds__(320, 1)
rnn_kernel(const float* __restrict__ W_hh, float* __restrict__ out)
{
    __shared__ float h_pub[NG][2][GB][64];     // [g][buf][b][row] 2 KB
    __shared__ float recv[NG][2][CSZ][128];    // [g][buf][src][lane*4+..] 8 KB
    __shared__ float stage[NG][2][CSZ][128];   // [g][buf][warp][lane*4+..] 8 KB
    __shared__ unsigned long long mbar[NG][2];

    const int tid  = threadIdx.x;
    unsigned int rank;
    asm("mov.u32 %0, %%cluster_ctarank;" : "=r"(rank));
    const int batch_base = (blockIdx.x / CSZ) * 4;

    // mbar addrs
    unsigned int mb_sa[NG][2];
#pragma unroll
    for (int g = 0; g < NG; g++)
#pragma unroll
        for (int b = 0; b < 2; b++)
            mb_sa[g][b] = (unsigned int)__cvta_generic_to_shared(&mbar[g][b]);

    if (tid == 0) {
#pragma unroll
        for (int g = 0; g < NG; g++)
#pragma unroll
            for (int b = 0; b < 2; b++) {
                asm volatile("mbarrier.init.shared.b64 [%0], 1;" :: "r"(mb_sa[g][b]) : "memory");
                asm volatile("mbarrier.arrive.expect_tx.shared.b64 _, [%0], %1;"
                             :: "r"(mb_sa[g][b]), "r"(GRP_TX) : "memory");
            }
    }
    if (tid < 256) {   // zero all h_pub (512 floats)
        ((float*)h_pub)[tid] = 0.0f;
        ((float*)h_pub)[tid + 256] = 0.0f;
    }
    __syncthreads();
    asm volatile("barrier.cluster.arrive.aligned;" ::: "memory");
    asm volatile("barrier.cluster.wait.aligned;"   ::: "memory");

    if (tid < 256) {
        // ================= COMPUTE ROLE =================
        const int w    = tid >> 5;     // warp 0..7 == destination CTA
        const int lane = tid & 31;

        unsigned long long Wp0[32], Wp1[32];   // 2 rows x 64 cols
        {
            const unsigned long long* wr0 =
                (const unsigned long long*)(W_hh + (size_t)(64 * w + lane) * HID + rank * 64);
            const unsigned long long* wr1 =
                (const unsigned long long*)(W_hh + (size_t)(64 * w + lane + 32) * HID + rank * 64);
#pragma unroll
            for (int i = 0; i < 32; i++) { Wp0[i] = wr0[i]; Wp1[i] = wr1[i]; }
        }

        const unsigned int stage_base =
            (unsigned int)__cvta_generic_to_shared(&stage[0][0][0][0]);
        unsigned int dst_ra[NG][2], mb_ra[NG][2];
#pragma unroll
        for (int g = 0; g < NG; g++)
#pragma unroll
            for (int b = 0; b < 2; b++) {
                unsigned int la = (unsigned int)
                    __cvta_generic_to_shared(&recv[g][b][rank][0]);
                asm("mapa.shared::cluster.u32 %0, %1, %2;"
                    : "=r"(dst_ra[g][b]) : "r"(la), "r"((unsigned)w));
                asm("mapa.shared::cluster.u32 %0, %1, %2;"
                    : "=r"(mb_ra[g][b]) : "r"(mb_sa[g][b]), "r"((unsigned)w));
            }

        for (int s = 0; s < S_LEN; s++) {
            const int cb = s & 1;
#pragma unroll
            for (int g = 0; g < NG; g++) {
                if (s > 0) {
                    // wait for h_pub[g][cb] published by reduce(g, s-1)
                    asm volatile("bar.sync %0, 320;" :: "r"(1 + g) : "memory");
                }
                float p0[GB], p1[GB];
#pragma unroll
                for (int b = 0; b < GB; b++) {
                    unsigned long long a0 = 0ull, a1 = 0ull, c0 = 0ull, c1 = 0ull;
                    const ulonglong2* hb = (const ulonglong2*)h_pub[g][cb][b];
#pragma unroll
                    for (int i = 0; i < 16; i++) {
                        ulonglong2 hv = hb[i];
                        ffma2(a0, Wp0[2 * i],     hv.x);
                        ffma2(a1, Wp0[2 * i + 1], hv.y);
                        ffma2(c0, Wp1[2 * i],     hv.x);
                        ffma2(c1, Wp1[2 * i + 1], hv.y);
                    }
                    unsigned long long sa, sc;
                    asm("add.rn.f32x2 %0, %1, %2;" : "=l"(sa) : "l"(a0), "l"(a1));
                    asm("add.rn.f32x2 %0, %1, %2;" : "=l"(sc) : "l"(c0), "l"(c1));
                    float2 fa = unpack2(sa), fc = unpack2(sc);
                    p0[b] = fa.x + fa.y;
                    p1[b] = fc.x + fc.y;
                }
                // layout: lane*4 + {p0[0], p0[1], p1[0], p1[1]}
                *(float4*)&stage[g][cb][w][lane * 4] =
                    make_float4(p0[0], p0[1], p1[0], p1[1]);
                __syncwarp();
                if (lane == 0) {
                    const unsigned int src_sa = stage_base +
                        (unsigned)((g * 2 + cb) * (CSZ * 512) + w * 512);
                    asm volatile("fence.proxy.async.shared::cta;" ::: "memory");
                    asm volatile(
                        "cp.async.bulk.shared::cluster.shared::cta.mbarrier::complete_tx::bytes "
                        "[%0], [%1], 512, [%2];"
                        :: "r"(dst_ra[g][cb]), "r"(src_sa), "r"(mb_ra[g][cb]) : "memory");
                }
            }
        }
    } else {
        // ================= REDUCE ROLE (64 threads) =================
        const int t = tid - 256;             // 0..63 == local row
        const int half_off = (t < 32) ? (t * 4) : ((t - 32) * 4 + 2);

        const float* xp_p[NG][GB];
        float*       out_p[NG][GB];
#pragma unroll
        for (int g = 0; g < NG; g++)
#pragma unroll
            for (int b = 0; b < GB; b++) {
                xp_p[g][b]  = g_xproj + (size_t)(batch_base + g * 2 + b) * S_LEN * HID
                                      + rank * 64 + t;
                out_p[g][b] = out     + (size_t)(batch_base + g * 2 + b) * S_LEN * HID
                                      + rank * 64 + t;
            }

        for (int s = 0; s < S_LEN; s++) {
            const int cb = s & 1;
            const int nb = cb ^ 1;
            const unsigned int parity = (unsigned)(s >> 1) & 1u;
#pragma unroll
            for (int g = 0; g < NG; g++) {
                // issue xp loads before the wait (latency overlapped)
                float x0 = __ldg(xp_p[g][0] + (size_t)s * HID);
                float x1 = __ldg(xp_p[g][1] + (size_t)s * HID);

                const unsigned int mb = mb_sa[g][cb];
                unsigned int done;
                asm volatile(
                    "{\n\t.reg .pred p;\n\t"
                    "mbarrier.try_wait.parity.acquire.cluster.shared::cta.b64 p, [%1], %2;\n\t"
                    "selp.b32 %0, 1, 0, p;\n\t}"
                    : "=r"(done) : "r"(mb), "r"(parity) : "memory");
                if (!done) {
                    asm volatile(
                        "{\n\t.reg .pred P1;\n\t"
                        "WL_%=:\n\t"
                        "mbarrier.try_wait.parity.acquire.cluster.shared::cta.b64 P1, [%0], %1, 0x989680;\n\t"
                        "@P1 bra.uni WD_%=;\n\t"
                        "bra.uni WL_%=;\n\t"
                        "WD_%=:\n\t}"
                        :: "r"(mb), "r"(parity) : "memory");
                }
                if (t == 0) {   // re-arm for next use (s+2), before bar.arrive
                    asm volatile("mbarrier.arrive.expect_tx.shared.b64 _, [%0], %1;"
                                 :: "r"(mb), "r"(GRP_TX) : "memory");
                }

                float s0 = x0, s1 = x1;
#pragma unroll
                for (int src = 0; src < CSZ; src++) {
                    float2 v = *(const float2*)&recv[g][cb][src][half_off];
                    s0 += v.x; s1 += v.y;
                }
                float h0 = tanhf(s0), h1 = tanhf(s1);
                h_pub[g][nb][0][t] = h0;
                h_pub[g][nb][1][t] = h1;
                out_p[g][0][(size_t)s * HID] = h0;
                out_p[g][1][(size_t)s * HID] = h1;
                if (s == S_LEN - 1) {
                    out[(size_t)BATCH * S_LEN * HID +
                        (size_t)(batch_base + g * 2 + 0) * HID + rank * 64 + t] = h0;
                    out[(size_t)BATCH * S_LEN * HID +
                        (size_t)(batch_base + g * 2 + 1) * HID + rank * 64 + t] = h1;
                } else {
                    asm volatile("bar.arrive %0, 320;" :: "r"(1 + g) : "memory");
                }
            }
        }
    }

    asm volatile("barrier.cluster.arrive.aligned;" ::: "memory");
    asm volatile("barrier.cluster.wait.aligned;"   ::: "memory");
}

// ---------------------------------------------------------------------------
// Launch
// ---------------------------------------------------------------------------
extern "C" void kernel_launch(void* const* d_in, const int* in_sizes, int n_in,
                              void* d_out, int out_size)
{
    const void*  tok  = d_in[0];                 // (B,S) int32 or int64
    const float* emb  = (const float*)d_in[1];   // (V,E)
    const float* W_ih = (const float*)d_in[2];   // (H,E)
    const float* W_hh = (const float*)d_in[3];   // (H,H)
    const float* b_ih = (const float*)d_in[4];   // (H,)
    const float* b_hh = (const float*)d_in[5];   // (H,)
    float* out = (float*)d_out;                  // (B,S,H) outputs ++ (1,B,H) hidden

    dim3 grid_p1(HID / 128, (BATCH * S_LEN) / 128);   // (4, 256)
    xproj_kernel<<<grid_p1, 256>>>(tok, emb, W_ih, b_ih, b_hh);

    rnn_kernel<<<(BATCH / 4) * CSZ, 320>>>(W_hh, out);  // 128 CTAs = 16 clusters
}